// round 3
// baseline (speedup 1.0000x reference)
#include <cuda_runtime.h>
#include <math_constants.h>

#define C_DIM 1024
#define N_DIM 1024
#define O_DIM 2048
#define K_NN  20

// ---------------- scratch (no allocations allowed) ----------------
__device__ float g_gram[N_DIM * N_DIM];   // 4 MB: G = x^T x
__device__ float g_x2[N_DIM];             // diag(G)
__device__ int   g_idx[N_DIM * K_NN];     // top-20 neighbor indices per column
__device__ float g_h[C_DIM * N_DIM];      // 4 MB: h = (1+eps)*x + x_sum

// ---------------- Kernel 1: Gram = x^T x ----------------
// x is (C, N) row-major. G[i][j] = sum_c x[c][i]*x[c][j].
// Both operand tiles load identically (contiguous along i/j). 64x64 tile, KT=16.
__global__ __launch_bounds__(256) void gram_kernel(const float* __restrict__ x,
                                                   float* __restrict__ G) {
    __shared__ float As[16][64];
    __shared__ float Bs[16][64];

    const int lt = threadIdx.x;          // 0..255
    const int tx = lt & 15;              // 0..15
    const int ty = lt >> 4;              // 0..15
    const int i0 = blockIdx.y * 64;
    const int j0 = blockIdx.x * 64;

    const int lk = lt >> 4;              // 0..15 (k within tile)
    const int li = (lt & 15) * 4;        // 0..60

    float acc[4][4];
#pragma unroll
    for (int r = 0; r < 4; r++)
#pragma unroll
        for (int s = 0; s < 4; s++) acc[r][s] = 0.f;

    for (int k0 = 0; k0 < C_DIM; k0 += 16) {
        float4 a = *(const float4*)&x[(k0 + lk) * N_DIM + i0 + li];
        float4 b = *(const float4*)&x[(k0 + lk) * N_DIM + j0 + li];
        *(float4*)&As[lk][li] = a;
        *(float4*)&Bs[lk][li] = b;
        __syncthreads();
#pragma unroll
        for (int kk = 0; kk < 16; kk++) {
            float4 av = *(const float4*)&As[kk][ty * 4];
            float4 bv = *(const float4*)&Bs[kk][tx * 4];
            float af[4] = {av.x, av.y, av.z, av.w};
            float bf[4] = {bv.x, bv.y, bv.z, bv.w};
#pragma unroll
            for (int r = 0; r < 4; r++)
#pragma unroll
                for (int s = 0; s < 4; s++) acc[r][s] = fmaf(af[r], bf[s], acc[r][s]);
        }
        __syncthreads();
    }

#pragma unroll
    for (int r = 0; r < 4; r++) {
        int i = i0 + ty * 4 + r;
#pragma unroll
        for (int s = 0; s < 4; s++) G[i * N_DIM + j0 + tx * 4 + s] = acc[r][s];
    }
}

// ---------------- Kernel 2: extract diag ----------------
__global__ void diag_kernel(const float* __restrict__ G, float* __restrict__ x2) {
    int n = blockIdx.x * blockDim.x + threadIdx.x;
    if (n < N_DIM) x2[n] = G[n * N_DIM + n];
}

// ---------------- Kernel 3: top-20 per row ----------------
// dist[i][j] = 2*G[i][j] - x2[i] - x2[j]; jax top_k tie-break = lowest index.
__global__ __launch_bounds__(256) void topk_kernel(const float* __restrict__ G,
                                                   const float* __restrict__ x2,
                                                   int* __restrict__ idx) {
    __shared__ float d[N_DIM];
    __shared__ float sv[256];
    __shared__ int   si[256];

    const int i = blockIdx.x;
    const int t = threadIdx.x;
    const float x2i = x2[i];

    for (int j = t; j < N_DIM; j += 256)
        d[j] = 2.f * G[i * N_DIM + j] - x2i - x2[j];
    __syncthreads();

    for (int k = 0; k < K_NN; k++) {
        float bv = -CUDART_INF_F;
        int   bi = N_DIM;
#pragma unroll
        for (int u = 0; u < 4; u++) {
            int j = t + u * 256;
            float v = d[j];
            if (v > bv || (v == bv && j < bi)) { bv = v; bi = j; }
        }
        sv[t] = bv; si[t] = bi;
        __syncthreads();
        for (int s = 128; s > 0; s >>= 1) {
            if (t < s) {
                float ov = sv[t + s]; int oi = si[t + s];
                if (ov > sv[t] || (ov == sv[t] && oi < si[t])) { sv[t] = ov; si[t] = oi; }
            }
            __syncthreads();
        }
        if (t == 0) {
            idx[i * K_NN + k] = si[0];
            d[si[0]] = -CUDART_INF_F;
        }
        __syncthreads();
    }
}

// ---------------- Kernel 4: h = (1+eps)*x + neighbor-sum ----------------
// block = one channel c; x row cached in smem so gathers stay on-chip.
__global__ __launch_bounds__(256) void h_kernel(const float* __restrict__ x,
                                                const float* __restrict__ eps,
                                                const int* __restrict__ idx,
                                                float* __restrict__ h) {
    __shared__ float xr[N_DIM];
    const int c = blockIdx.x;
    const int t = threadIdx.x;

    for (int j = t; j < N_DIM; j += 256) xr[j] = x[c * N_DIM + j];
    __syncthreads();

    for (int n = t; n < N_DIM; n += 256) {
        const int* ip = &idx[n * K_NN];
        float s = 0.f;
#pragma unroll
        for (int k = 0; k < K_NN; k++) s += xr[ip[k]];
        float xn = xr[n];
        h[c * N_DIM + n] = xn + eps[c * N_DIM + n] * xn + s;
    }
}

// ---------------- Kernel 5: out = W @ h ----------------
// W (O, C) row-major (contiguous along k); h (C, N). 64x64 tile, KT=16.
__global__ __launch_bounds__(256) void out_gemm_kernel(const float* __restrict__ W,
                                                       const float* __restrict__ h,
                                                       float* __restrict__ out) {
    __shared__ float As[16][65];   // [kk][oo], padded to kill transpose-store conflicts
    __shared__ float Bs[16][64];   // [kk][nn]

    const int lt = threadIdx.x;
    const int tx = lt & 15;
    const int ty = lt >> 4;
    const int o0 = blockIdx.y * 64;
    const int n0 = blockIdx.x * 64;

    const int oo = lt >> 2;            // 0..63
    const int kq = (lt & 3) * 4;       // 0,4,8,12
    const int lk = lt >> 4;            // 0..15
    const int ln = (lt & 15) * 4;      // 0..60

    float acc[4][4];
#pragma unroll
    for (int r = 0; r < 4; r++)
#pragma unroll
        for (int s = 0; s < 4; s++) acc[r][s] = 0.f;

    for (int k0 = 0; k0 < C_DIM; k0 += 16) {
        float4 w = *(const float4*)&W[(o0 + oo) * C_DIM + k0 + kq];
        As[kq + 0][oo] = w.x;
        As[kq + 1][oo] = w.y;
        As[kq + 2][oo] = w.z;
        As[kq + 3][oo] = w.w;
        *(float4*)&Bs[lk][ln] = *(const float4*)&h[(k0 + lk) * N_DIM + n0 + ln];
        __syncthreads();
#pragma unroll
        for (int kk = 0; kk < 16; kk++) {
            float af[4];
#pragma unroll
            for (int r = 0; r < 4; r++) af[r] = As[kk][ty * 4 + r];
            float4 bv = *(const float4*)&Bs[kk][tx * 4];
            float bf[4] = {bv.x, bv.y, bv.z, bv.w};
#pragma unroll
            for (int r = 0; r < 4; r++)
#pragma unroll
                for (int s = 0; s < 4; s++) acc[r][s] = fmaf(af[r], bf[s], acc[r][s]);
        }
        __syncthreads();
    }

#pragma unroll
    for (int r = 0; r < 4; r++) {
        int o = o0 + ty * 4 + r;
#pragma unroll
        for (int s = 0; s < 4; s++) out[o * N_DIM + n0 + tx * 4 + s] = acc[r][s];
    }
}

// ---------------- launch ----------------
extern "C" void kernel_launch(void* const* d_in, const int* in_sizes, int n_in,
                              void* d_out, int out_size) {
    const float* x   = (const float*)d_in[0];   // (C, N)
    const float* W   = (const float*)d_in[1];   // (O, C, 1, 1)
    const float* eps = (const float*)d_in[2];   // (C, N, 1)
    float* out = (float*)d_out;                 // (O, N)

    float* gram; cudaGetSymbolAddress((void**)&gram, g_gram);
    float* x2;   cudaGetSymbolAddress((void**)&x2,   g_x2);
    int*   idx;  cudaGetSymbolAddress((void**)&idx,  g_idx);
    float* h;    cudaGetSymbolAddress((void**)&h,    g_h);

    gram_kernel<<<dim3(N_DIM / 64, N_DIM / 64), 256>>>(x, gram);
    diag_kernel<<<N_DIM / 256, 256>>>(gram, x2);
    topk_kernel<<<N_DIM, 256>>>(gram, x2, idx);
    h_kernel<<<C_DIM, 256>>>(x, eps, idx, h);
    out_gemm_kernel<<<dim3(N_DIM / 64, O_DIM / 64), 256>>>(W, h, out);
}

// round 5
// speedup vs baseline: 1.3426x; 1.3426x over previous
#include <cuda_runtime.h>
#include <math_constants.h>
#include <cstdint>

#define CD 1024
#define ND 1024
#define OD 2048
#define KNN 20

// ---------------- scratch ----------------
__device__ float g_xT[ND * CD];     // x^T  (N, C) K-major
__device__ float g_eT[ND * CD];     // eps^T (N, C)
__device__ float g_gram[ND * ND];   // G = x^T x
__device__ float g_x2[ND];
__device__ int   g_idx[ND * KNN];
__device__ float g_hT[ND * CD];     // h^T (N, C) K-major

// ---------------- helpers ----------------
__device__ __forceinline__ void split_tf32(float x, float& h, float& l) {
    uint32_t u;
    asm("cvt.rna.tf32.f32 %0, %1;" : "=r"(u) : "f"(x));
    h = __uint_as_float(u);
    float r = x - h;                      // exact in fp32
    asm("cvt.rna.tf32.f32 %0, %1;" : "=r"(u) : "f"(r));
    l = __uint_as_float(u);
}

__device__ __forceinline__ void mma_tf32(float4& c, const float4& a, const float2& b) {
    asm volatile(
        "mma.sync.aligned.m16n8k8.row.col.f32.tf32.tf32.f32 "
        "{%0,%1,%2,%3}, {%4,%5,%6,%7}, {%8,%9}, {%0,%1,%2,%3};"
        : "+f"(c.x), "+f"(c.y), "+f"(c.z), "+f"(c.w)
        : "r"(__float_as_uint(a.x)), "r"(__float_as_uint(a.y)),
          "r"(__float_as_uint(a.z)), "r"(__float_as_uint(a.w)),
          "r"(__float_as_uint(b.x)), "r"(__float_as_uint(b.y)));
}

// ================= split-TF32 GEMM via mma.sync =================
// D[M,N] = A[M,K] * B[N,K]^T ; A,B fp32 K-major (K = CD), 2-term tf32 split,
// 3 MMA passes (hh, lh, hl). CTA tile 128 x NT, 128 threads (2x2 warps),
// warp tile 64 x NT/2. SMEM holds one K-chunk of 32 in MMA-frag packing.
template <int NT>
__global__ __launch_bounds__(128, 2)
void mma_gemm(const float* __restrict__ A, const float* __restrict__ B,
              float* __restrict__ D, int ldd) {
    constexpr int K    = CD;
    constexpr int ASTR = 64 * 16 + 8;   // floats per k8 block (padded)
    constexpr int ASZ  = 4 * ASTR;      // 4128 floats
    constexpr int BROW = NT * 2 + 4;    // floats per (k8,kq) row (padded)
    constexpr int BSZ  = 16 * BROW;
    constexpr int WN   = NT / 2;        // warp n extent
    constexpr int NTN  = WN / 8;        // n-tiles per warp

    extern __shared__ float sm[];
    float* sAh = sm;
    float* sAl = sm + ASZ;
    float* sBh = sm + 2 * ASZ;
    float* sBl = sm + 2 * ASZ + BSZ;

    const int t    = threadIdx.x;
    const int wid  = t >> 5;
    const int lane = t & 31;
    const int wm   = (wid >> 1) * 64;   // warp m offset: 0 / 64
    const int wn   = (wid & 1) * WN;    // warp n offset
    const int lq   = lane & 3;          // kq
    const int lg   = lane >> 2;         // 0..7
    const int m0   = blockIdx.y * 128;
    const int n0   = blockIdx.x * NT;

    float4 c[4][NTN];
#pragma unroll
    for (int mt = 0; mt < 4; mt++)
#pragma unroll
        for (int nt = 0; nt < NTN; nt++) c[mt][nt] = make_float4(0.f, 0.f, 0.f, 0.f);

    for (int i = 0; i < K / 32; i++) {
        const int k0 = i * 32;

        // ---- load + split A chunk: 128 rows x 32 k ----
#pragma unroll
        for (int j = 0; j < 4; j++) {
            int u    = t + j * 128;
            int kgrp = u & 7;                 // which float4 along k
            int rid  = u >> 3;                // 0..63 (row-pair id == rgrp)
            int r    = ((rid >> 3) << 4) + (rid & 7);
            int k8   = kgrp >> 1, kh = kgrp & 1;
            const float* pa = &A[(size_t)(m0 + r) * K + k0 + kgrp * 4];
            float4 va = *(const float4*)pa;
            float4 vb = *(const float4*)(pa + 8 * K);   // row r+8
            int base = k8 * ASTR + rid * 16 + 2 * kh;
            float h0, l0, h1, l1;
            split_tf32(va.x, h0, l0); split_tf32(vb.x, h1, l1);
            *(float2*)&sAh[base +  0] = make_float2(h0, h1);
            *(float2*)&sAl[base +  0] = make_float2(l0, l1);
            split_tf32(va.y, h0, l0); split_tf32(vb.y, h1, l1);
            *(float2*)&sAh[base +  4] = make_float2(h0, h1);
            *(float2*)&sAl[base +  4] = make_float2(l0, l1);
            split_tf32(va.z, h0, l0); split_tf32(vb.z, h1, l1);
            *(float2*)&sAh[base +  8] = make_float2(h0, h1);
            *(float2*)&sAl[base +  8] = make_float2(l0, l1);
            split_tf32(va.w, h0, l0); split_tf32(vb.w, h1, l1);
            *(float2*)&sAh[base + 12] = make_float2(h0, h1);
            *(float2*)&sAl[base + 12] = make_float2(l0, l1);
        }
        // ---- load + split B chunk: NT rows x 32 k ----
#pragma unroll
        for (int j = 0; j < NT / 32; j++) {
            int u  = t + j * 128;
            int n  = u >> 2;                  // row within tile
            int k8 = u & 3;
            const float* pb = &B[(size_t)(n0 + n) * K + k0 + k8 * 8];
            float4 v0 = *(const float4*)pb;
            float4 v1 = *(const float4*)(pb + 4);
            float h0, l0, h1, l1;
            int base = (k8 * 4) * BROW + n * 2;
            split_tf32(v0.x, h0, l0); split_tf32(v1.x, h1, l1);
            *(float2*)&sBh[base + 0 * BROW] = make_float2(h0, h1);
            *(float2*)&sBl[base + 0 * BROW] = make_float2(l0, l1);
            split_tf32(v0.y, h0, l0); split_tf32(v1.y, h1, l1);
            *(float2*)&sBh[base + 1 * BROW] = make_float2(h0, h1);
            *(float2*)&sBl[base + 1 * BROW] = make_float2(l0, l1);
            split_tf32(v0.z, h0, l0); split_tf32(v1.z, h1, l1);
            *(float2*)&sBh[base + 2 * BROW] = make_float2(h0, h1);
            *(float2*)&sBl[base + 2 * BROW] = make_float2(l0, l1);
            split_tf32(v0.w, h0, l0); split_tf32(v1.w, h1, l1);
            *(float2*)&sBh[base + 3 * BROW] = make_float2(h0, h1);
            *(float2*)&sBl[base + 3 * BROW] = make_float2(l0, l1);
        }
        __syncthreads();

        // ---- 3 split passes x 4 k8 steps ----
#pragma unroll
        for (int pair = 0; pair < 3; pair++) {
            const float* Ab = (pair == 1) ? sAl : sAh;
            const float* Bb = (pair == 2) ? sBl : sBh;
#pragma unroll
            for (int k8 = 0; k8 < 4; k8++) {
                float4 a[4];
                float2 b[NTN];
#pragma unroll
                for (int mt = 0; mt < 4; mt++)
                    a[mt] = *(const float4*)&Ab[k8 * ASTR +
                        (((wm >> 4) + mt) * 8 + lg) * 16 + lq * 4];
#pragma unroll
                for (int nt = 0; nt < NTN; nt++)
                    b[nt] = *(const float2*)&Bb[(k8 * 4 + lq) * BROW +
                        (wn + nt * 8 + lg) * 2];
#pragma unroll
                for (int mt = 0; mt < 4; mt++)
#pragma unroll
                    for (int nt = 0; nt < NTN; nt++)
                        mma_tf32(c[mt][nt], a[mt], b[nt]);
            }
        }
        __syncthreads();
    }

    // ---- epilogue ----
#pragma unroll
    for (int mt = 0; mt < 4; mt++) {
        int r0 = m0 + wm + mt * 16 + lg;
#pragma unroll
        for (int nt = 0; nt < NTN; nt++) {
            int cb = n0 + wn + nt * 8 + lq * 2;
            *(float2*)&D[(size_t)r0 * ldd + cb]       = make_float2(c[mt][nt].x, c[mt][nt].y);
            *(float2*)&D[(size_t)(r0 + 8) * ldd + cb] = make_float2(c[mt][nt].z, c[mt][nt].w);
        }
    }
}

// ================= transpose x and eps =================
__global__ __launch_bounds__(256) void transpose_kernel(
    const float* __restrict__ x, const float* __restrict__ e,
    float* __restrict__ xT, float* __restrict__ eT) {
    __shared__ float tx[32][33], te[32][33];
    const int i0 = blockIdx.x * 32;   // N dim
    const int j0 = blockIdx.y * 32;   // C dim
    const int c = threadIdx.x, r = threadIdx.y;
#pragma unroll
    for (int k = 0; k < 32; k += 8) {
        tx[r + k][c] = x[(size_t)(j0 + r + k) * ND + i0 + c];
        te[r + k][c] = e[(size_t)(j0 + r + k) * ND + i0 + c];
    }
    __syncthreads();
#pragma unroll
    for (int k = 0; k < 32; k += 8) {
        xT[(size_t)(i0 + r + k) * CD + j0 + c] = tx[c][r + k];
        eT[(size_t)(i0 + r + k) * CD + j0 + c] = te[c][r + k];
    }
}

// ================= diag =================
__global__ void diag_kernel(const float* __restrict__ G, float* __restrict__ x2) {
    int n = blockIdx.x * blockDim.x + threadIdx.x;
    if (n < ND) x2[n] = G[(size_t)n * ND + n];
}

// ================= top-20 (shuffle argmax) =================
__global__ __launch_bounds__(256) void topk_kernel(const float* __restrict__ G,
                                                   const float* __restrict__ x2,
                                                   int* __restrict__ idx) {
    __shared__ float d[ND];
    __shared__ float sv[8];
    __shared__ int   si[8];
    const int i = blockIdx.x;
    const int t = threadIdx.x;
    const int w = t >> 5, lane = t & 31;
    const float x2i = x2[i];

    for (int j = t; j < ND; j += 256)
        d[j] = 2.f * G[(size_t)i * ND + j] - x2i - x2[j];
    __syncthreads();

    for (int k = 0; k < KNN; k++) {
        float bv = -CUDART_INF_F;
        int   bi = ND;
#pragma unroll
        for (int u = 0; u < 4; u++) {
            int j = t + u * 256;
            float v = d[j];
            if (v > bv || (v == bv && j < bi)) { bv = v; bi = j; }
        }
#pragma unroll
        for (int off = 16; off > 0; off >>= 1) {
            float ov = __shfl_xor_sync(0xffffffffu, bv, off);
            int   oi = __shfl_xor_sync(0xffffffffu, bi, off);
            if (ov > bv || (ov == bv && oi < bi)) { bv = ov; bi = oi; }
        }
        if (lane == 0) { sv[w] = bv; si[w] = bi; }
        __syncthreads();
        if (w == 0) {
            float v2 = (lane < 8) ? sv[lane] : -CUDART_INF_F;
            int   i2 = (lane < 8) ? si[lane] : ND;
#pragma unroll
            for (int off = 4; off > 0; off >>= 1) {
                float ov = __shfl_xor_sync(0xffffffffu, v2, off);
                int   oi = __shfl_xor_sync(0xffffffffu, i2, off);
                if (ov > v2 || (ov == v2 && oi < i2)) { v2 = ov; i2 = oi; }
            }
            if (lane == 0) { idx[i * KNN + k] = i2; d[i2] = -CUDART_INF_F; }
        }
        __syncthreads();
    }
}

// ================= hT = ((1+eps)*x + neighbor-sum)^T =================
__global__ __launch_bounds__(256) void hT_kernel(const float* __restrict__ xT,
                                                 const float* __restrict__ eT,
                                                 const int* __restrict__ idx,
                                                 float* __restrict__ hT) {
    __shared__ int nb[KNN];
    const int n = blockIdx.x;
    const int t = threadIdx.x;
    if (t < KNN) nb[t] = idx[n * KNN + t];
    __syncthreads();

    const int c4 = t;  // CD/4 == 256 == blockDim
    const size_t base = (size_t)n * CD + c4 * 4;
    float4 xv = *(const float4*)&xT[base];
    float4 ev = *(const float4*)&eT[base];
    float4 s;
    s.x = fmaf(ev.x, xv.x, xv.x);
    s.y = fmaf(ev.y, xv.y, xv.y);
    s.z = fmaf(ev.z, xv.z, xv.z);
    s.w = fmaf(ev.w, xv.w, xv.w);
#pragma unroll
    for (int k = 0; k < KNN; k++) {
        float4 nv = *(const float4*)&xT[(size_t)nb[k] * CD + c4 * 4];
        s.x += nv.x; s.y += nv.y; s.z += nv.z; s.w += nv.w;
    }
    *(float4*)&hT[base] = s;
}

// ================= launch =================
extern "C" void kernel_launch(void* const* d_in, const int* in_sizes, int n_in,
                              void* d_out, int out_size) {
    const float* x   = (const float*)d_in[0];   // (C, N)
    const float* W   = (const float*)d_in[1];   // (O, C)
    const float* eps = (const float*)d_in[2];   // (C, N)
    float* out = (float*)d_out;                 // (O, N)

    float* xT;   cudaGetSymbolAddress((void**)&xT,   g_xT);
    float* eT;   cudaGetSymbolAddress((void**)&eT,   g_eT);
    float* gram; cudaGetSymbolAddress((void**)&gram, g_gram);
    float* x2;   cudaGetSymbolAddress((void**)&x2,   g_x2);
    int*   idx;  cudaGetSymbolAddress((void**)&idx,  g_idx);
    float* hT;   cudaGetSymbolAddress((void**)&hT,   g_hT);

    // dynamic smem: 2*ASZ + 2*BSZ floats
    const int SMEM64  = (2 * 4128 + 2 * (16 * (64 * 2 + 4))) * 4;    // 49920
    const int SMEM128 = (2 * 4128 + 2 * (16 * (128 * 2 + 4))) * 4;   // 66304
    cudaFuncSetAttribute(mma_gemm<64>,  cudaFuncAttributeMaxDynamicSharedMemorySize, SMEM64);
    cudaFuncSetAttribute(mma_gemm<128>, cudaFuncAttributeMaxDynamicSharedMemorySize, SMEM128);

    transpose_kernel<<<dim3(ND / 32, CD / 32), dim3(32, 8)>>>(x, eps, xT, eT);
    // Gram: M=1024 (rows of xT), N=1024, CTA 128x64 -> 128 CTAs
    mma_gemm<64><<<dim3(ND / 64, ND / 128), 128, SMEM64>>>(xT, xT, gram, ND);
    diag_kernel<<<ND / 256, 256>>>(gram, x2);
    topk_kernel<<<ND, 256>>>(gram, x2, idx);
    hT_kernel<<<ND, 256>>>(xT, eT, idx, hT);
    // Out: M=2048 (rows of W), N=1024, CTA 128x128 -> 128 CTAs
    mma_gemm<128><<<dim3(ND / 128, OD / 128), 128, SMEM128>>>(W, hT, out, ND);
}